// round 7
// baseline (speedup 1.0000x reference)
#include <cuda_runtime.h>

#define NN   50000
#define NG   32
#define NF   16
#define GF   2
#define HID  300
#define LATD 100
#define NE   800000
#define TE   64
#define STR  66   // smem row stride for transposed tiles (bank-conflict pad, even for LDS.64)

typedef unsigned long long u64;
typedef long long i64;

// -------- scratch (device globals; no allocation allowed) --------
__device__ float g_B[NN * HID];     // per-node  x @ W_bot
__device__ float g_C[NN * HID];     // per-node  x @ (W_top - W_bot) + b1
__device__ float g_acc[NN * LATD];  // scatter accumulator
__device__ float g_x1[NN * LATD];   // node features between layers
__device__ float g_cnt[NN];         // in-degree (float for direct divide)
__device__ float g_pool[NG * LATD]; // graph pooling sums
__device__ float g_gcnt[NG];        // nodes per graph
__device__ int   g_src[NE];         // normalized int32 edge sources
__device__ int   g_dst[NE];         // normalized int32 edge dests
__device__ int   g_batch[NN];       // normalized int32 batch ids
__device__ int   g_is64;            // dtype probe result

// -------- f32x2 helpers (FFMA2: 2x FP32 FMA throughput, PTX-only) --------
__device__ __forceinline__ u64 splat2(float v) {
    u64 r; unsigned iv = __float_as_uint(v);
    asm("mov.b64 %0, {%1, %1};" : "=l"(r) : "r"(iv));
    return r;
}
__device__ __forceinline__ u64 fma2(u64 a, u64 b, u64 c) {
    u64 d;
    asm("fma.rn.f32x2 %0, %1, %2, %3;" : "=l"(d) : "l"(a), "l"(b), "l"(c));
    return d;
}
__device__ __forceinline__ void unpack2(u64 v, float& lo, float& hi) {
    unsigned a, b;
    asm("mov.b64 {%0, %1}, %2;" : "=r"(a), "=r"(b) : "l"(v));
    lo = __uint_as_float(a); hi = __uint_as_float(b);
}

// -------- dtype probe: are index inputs int64 or int32? --------
// If truly int64: every value < 50000 < 2^32. If int32 narrowed: a u64 read
// combines two random indices in [0,50000) -> >= 2^32 w.p. ~1 per element.
__global__ void k_probe(const void* ei) {
    const u64* p = (const u64*)ei;
    int is64 = 1;
    for (int i = 0; i < 16; i++)
        if (p[i] >= (1ull << 32)) is64 = 0;
    g_is64 = is64;
}

// Normalize edge_index + batch into int32 device arrays (handles both dtypes).
__global__ void k_convert(const void* ei, const void* batch) {
    int i = blockIdx.x * blockDim.x + threadIdx.x;
    if (g_is64) {
        const i64* e = (const i64*)ei;
        const i64* b = (const i64*)batch;
        if (i < NE) { g_src[i] = (int)e[i]; g_dst[i] = (int)e[NE + i]; }
        if (i < NN) g_batch[i] = (int)b[i];
    } else {
        const int* e = (const int*)ei;
        const int* b = (const int*)batch;
        if (i < NE) { g_src[i] = e[i]; g_dst[i] = e[NE + i]; }
        if (i < NN) g_batch[i] = b[i];
    }
}

// -------- zero / count kernels --------
__global__ void k_zero_all() {
    int i = blockIdx.x * blockDim.x + threadIdx.x;
    int st = gridDim.x * blockDim.x;
    for (int j = i; j < NN * LATD; j += st) g_acc[j] = 0.f;
    for (int j = i; j < NN; j += st) g_cnt[j] = 0.f;
    for (int j = i; j < NG * LATD; j += st) g_pool[j] = 0.f;
    for (int j = i; j < NG; j += st) g_gcnt[j] = 0.f;
}
__global__ void k_zero_acc() {
    int i = blockIdx.x * blockDim.x + threadIdx.x;
    int st = gridDim.x * blockDim.x;
    for (int j = i; j < NN * LATD; j += st) g_acc[j] = 0.f;
}
__global__ void k_counts() {
    int i = blockIdx.x * blockDim.x + threadIdx.x;
    if (i < NE) atomicAdd(&g_cnt[g_dst[i]], 1.f);
    if (i < NN) atomicAdd(&g_gcnt[g_batch[i]], 1.f);
}

// -------- node precompute: B = x@W_bot, C = x@(W_top - W_bot) + b1 --------
// thread computes 4 consecutive h's (float4 weight loads; 300 = 75*4)
template <int INF>
__global__ void k_node_pre(const float* __restrict__ x,
                           const float* __restrict__ w1,
                           const float* __restrict__ b1) {
    int i = blockIdx.x * blockDim.x + threadIdx.x;
    if (i >= NN * (HID / 4)) return;
    int n = i / (HID / 4);
    int h4 = (i - n * (HID / 4)) * 4;
    const float* xr = x + n * INF;
    float4 a = make_float4(0.f, 0.f, 0.f, 0.f);
    float4 b = make_float4(0.f, 0.f, 0.f, 0.f);
#pragma unroll 8
    for (int f = 0; f < INF; f++) {
        float xv = __ldg(xr + f);
        float4 wt = *(const float4*)(w1 + f * HID + h4);
        float4 wb = *(const float4*)(w1 + (INF + f) * HID + h4);
        a.x = fmaf(xv, wt.x, a.x); a.y = fmaf(xv, wt.y, a.y);
        a.z = fmaf(xv, wt.z, a.z); a.w = fmaf(xv, wt.w, a.w);
        b.x = fmaf(xv, wb.x, b.x); b.y = fmaf(xv, wb.y, b.y);
        b.z = fmaf(xv, wb.z, b.z); b.w = fmaf(xv, wb.w, b.w);
    }
    float4 bb = *(const float4*)(b1 + h4);
    int o = n * HID + h4;
    *(float4*)(g_B + o) = b;
    float4 c = make_float4(a.x - b.x + bb.x, a.y - b.y + bb.y,
                           a.z - b.z + bb.z, a.w - b.w + bb.w);
    *(float4*)(g_C + o) = c;
}

// -------- fused edge MLP: 64 edges/CTA, FFMA2 register-tiled GEMM chain --------
// h1 = relu(C[dst] + B[src])            [64,300]  (smem, transposed)
// h2 = relu(h1 @ w2 + b2)               [64,300]  (smem, transposed)
// m  = h2 @ w3 + b3                     [64,100]  -> atomic scatter to g_acc[dst]
__global__ void __launch_bounds__(256) k_edge(const float* __restrict__ w2,
                                              const float* __restrict__ b2,
                                              const float* __restrict__ w3,
                                              const float* __restrict__ b3) {
    extern __shared__ float smem[];
    int* s_src = (int*)smem;            // 64 ints
    int* s_dst = s_src + TE;            // 64 ints
    float* shA  = smem + 128;           // [300][66] h1^T
    float* shH2 = shA + HID * STR;      // [300][66] h2^T
    float* shB  = shH2 + HID * STR;     // weight staging: 2*10*320 floats (reused 2*10*128)

    const int tid = threadIdx.x;
    const int tx = tid & 31, ty = tid >> 5;
    const int e0 = blockIdx.x * TE;

    if (tid < TE) {
        s_src[tid] = g_src[e0 + tid];
        s_dst[tid] = g_dst[e0 + tid];
    }
    __syncthreads();

    // gather: h1^T[k][r] = relu(C[dst_r][k] + B[src_r][k]), float2 global loads
    for (int idx = tid; idx < TE * (HID / 2); idx += 256) {
        int r = idx / (HID / 2);
        int k2 = (idx - r * (HID / 2)) * 2;
        const float2 cv = *(const float2*)(g_C + s_dst[r] * HID + k2);
        const float2 bv = *(const float2*)(g_B + s_src[r] * HID + k2);
        shA[k2 * STR + r]       = fmaxf(cv.x + bv.x, 0.f);
        shA[(k2 + 1) * STR + r] = fmaxf(cv.y + bv.y, 0.f);
    }
    __syncthreads();

    // ---------------- GEMM1: [64,300] @ w2[300,300] (cols padded to 320) ----------------
    // thread tile: 8 rows (4 f32x2 pairs) x 10 cols (5 col-pairs, stride 64)
    u64 acc[4][5][2];
#pragma unroll
    for (int p = 0; p < 4; p++)
#pragma unroll
        for (int t = 0; t < 5; t++) { acc[p][t][0] = 0ull; acc[p][t][1] = 0ull; }

    float sreg[13];
#pragma unroll
    for (int q = 0; q < 13; q++) {
        int i2 = tid + 256 * q;
        if (i2 < 3200) {
            int kk = i2 / 320, j = i2 - kk * 320;
            sreg[q] = (j < HID) ? __ldg(w2 + kk * HID + j) : 0.f;
        }
    }
#pragma unroll
    for (int q = 0; q < 13; q++) {
        int i2 = tid + 256 * q;
        if (i2 < 3200) shB[i2] = sreg[q];
    }
    __syncthreads();

    int buf = 0;
#pragma unroll 1
    for (int kc = 0; kc < 30; kc++) {
        int k0 = kc * 10;
        if (kc < 29) {
            int kn = k0 + 10;
#pragma unroll
            for (int q = 0; q < 13; q++) {
                int i2 = tid + 256 * q;
                if (i2 < 3200) {
                    int kk = i2 / 320, j = i2 - kk * 320;
                    sreg[q] = (j < HID) ? __ldg(w2 + (kn + kk) * HID + j) : 0.f;
                }
            }
        }
        const float* bBase = shB + buf * 3200;
#pragma unroll
        for (int kk = 0; kk < 10; kk++) {
            const float* aR = shA + (k0 + kk) * STR + ty * 8;
            u64 av[4];
#pragma unroll
            for (int p = 0; p < 4; p++) av[p] = *(const u64*)(aR + 2 * p);
            const float* bR = bBase + kk * 320 + tx * 2;
#pragma unroll
            for (int t = 0; t < 5; t++) {
                float2 bv = *(const float2*)(bR + 64 * t);
                u64 bx = splat2(bv.x), by = splat2(bv.y);
#pragma unroll
                for (int p = 0; p < 4; p++) {
                    acc[p][t][0] = fma2(av[p], bx, acc[p][t][0]);
                    acc[p][t][1] = fma2(av[p], by, acc[p][t][1]);
                }
            }
        }
        if (kc < 29) {
#pragma unroll
            for (int q = 0; q < 13; q++) {
                int i2 = tid + 256 * q;
                if (i2 < 3200) shB[(buf ^ 1) * 3200 + i2] = sreg[q];
            }
        }
        __syncthreads();
        buf ^= 1;
    }

    // epilogue GEMM1: h2^T = relu(acc + b2)
#pragma unroll
    for (int t = 0; t < 5; t++) {
#pragma unroll
        for (int c = 0; c < 2; c++) {
            int j = 64 * t + tx * 2 + c;
            if (j < HID) {
                float bb = __ldg(b2 + j);
#pragma unroll
                for (int p = 0; p < 4; p++) {
                    float lo, hi; unpack2(acc[p][t][c], lo, hi);
                    int r0 = ty * 8 + 2 * p;
                    float2 v;
                    v.x = fmaxf(lo + bb, 0.f);
                    v.y = fmaxf(hi + bb, 0.f);
                    *(float2*)(shH2 + j * STR + r0) = v;
                }
            }
        }
    }

    // prefetch GEMM2 chunk 0 (registers only) while epilogue drains
    float sreg2[5];
#pragma unroll
    for (int q = 0; q < 5; q++) {
        int i2 = tid + 256 * q;
        if (i2 < 1280) {
            int kk = i2 / 128, j = i2 - kk * 128;
            sreg2[q] = (j < LATD) ? __ldg(w3 + kk * LATD + j) : 0.f;
        }
    }
    __syncthreads();   // shH2 writes + shB reads complete
#pragma unroll
    for (int q = 0; q < 5; q++) {
        int i2 = tid + 256 * q;
        if (i2 < 1280) shB[i2] = sreg2[q];
    }
    __syncthreads();

    // ---------------- GEMM2: [64,300] @ w3[300,100] (cols padded to 128) ----------------
    u64 accB[4][2][2];
#pragma unroll
    for (int p = 0; p < 4; p++)
#pragma unroll
        for (int t = 0; t < 2; t++) { accB[p][t][0] = 0ull; accB[p][t][1] = 0ull; }

    buf = 0;
#pragma unroll 1
    for (int kc = 0; kc < 30; kc++) {
        int k0 = kc * 10;
        if (kc < 29) {
            int kn = k0 + 10;
#pragma unroll
            for (int q = 0; q < 5; q++) {
                int i2 = tid + 256 * q;
                if (i2 < 1280) {
                    int kk = i2 / 128, j = i2 - kk * 128;
                    sreg2[q] = (j < LATD) ? __ldg(w3 + (kn + kk) * LATD + j) : 0.f;
                }
            }
        }
        const float* bBase = shB + buf * 1280;
#pragma unroll
        for (int kk = 0; kk < 10; kk++) {
            const float* aR = shH2 + (k0 + kk) * STR + ty * 8;
            u64 av[4];
#pragma unroll
            for (int p = 0; p < 4; p++) av[p] = *(const u64*)(aR + 2 * p);
            const float* bR = bBase + kk * 128 + tx * 2;
#pragma unroll
            for (int t = 0; t < 2; t++) {
                float2 bv = *(const float2*)(bR + 64 * t);
                u64 bx = splat2(bv.x), by = splat2(bv.y);
#pragma unroll
                for (int p = 0; p < 4; p++) {
                    accB[p][t][0] = fma2(av[p], bx, accB[p][t][0]);
                    accB[p][t][1] = fma2(av[p], by, accB[p][t][1]);
                }
            }
        }
        if (kc < 29) {
#pragma unroll
            for (int q = 0; q < 5; q++) {
                int i2 = tid + 256 * q;
                if (i2 < 1280) shB[(buf ^ 1) * 1280 + i2] = sreg2[q];
            }
        }
        __syncthreads();
        buf ^= 1;
    }

    // epilogue GEMM2: m = acc + b3, atomic scatter-sum to g_acc[dst]
#pragma unroll
    for (int t = 0; t < 2; t++) {
#pragma unroll
        for (int c = 0; c < 2; c++) {
            int j = 64 * t + tx * 2 + c;
            if (j < LATD) {
                float b3j = __ldg(b3 + j);
#pragma unroll
                for (int p = 0; p < 4; p++) {
                    float lo, hi; unpack2(accB[p][t][c], lo, hi);
                    int r0 = ty * 8 + 2 * p;
                    atomicAdd(g_acc + s_dst[r0] * LATD + j,     lo + b3j);
                    atomicAdd(g_acc + s_dst[r0 + 1] * LATD + j, hi + b3j);
                }
            }
        }
    }
}

// -------- finalize: scatter-mean + relu --------
__global__ void k_fin0() {
    int i = blockIdx.x * blockDim.x + threadIdx.x;
    if (i >= NN * LATD) return;
    int n = i / LATD;
    float v = g_acc[i] / fmaxf(g_cnt[n], 1.f);
    g_x1[i] = fmaxf(v, 0.f);
}
__global__ void k_fin1() {
    int i = blockIdx.x * blockDim.x + threadIdx.x;
    if (i >= NN * LATD) return;
    int n = i / LATD;
    int j = i - n * LATD;
    float v = fmaxf(g_acc[i] / fmaxf(g_cnt[n], 1.f), 0.f);
    atomicAdd(g_pool + g_batch[n] * LATD + j, v);
}

// -------- head MLP: [32,102] -> 100 -> 100 -> 1 (single CTA) --------
__global__ void k_head(const float* __restrict__ u,
                       const float* __restrict__ w1, const float* __restrict__ b1,
                       const float* __restrict__ w2, const float* __restrict__ b2,
                       const float* __restrict__ w3, const float* __restrict__ b3,
                       float* __restrict__ out) {
    __shared__ float sp[NG][LATD + GF];
    __shared__ float sh[NG][LATD];
    __shared__ float sh2[NG][LATD];
    int tid = threadIdx.x;  // 128
    for (int i = tid; i < NG * LATD; i += 128) {
        int g = i / LATD, j = i - g * LATD;
        sp[g][j] = g_pool[i] / fmaxf(g_gcnt[g], 1.f);
    }
    for (int i = tid; i < NG * GF; i += 128) {
        int g = i / GF;
        sp[g][LATD + (i - g * GF)] = u[i];
    }
    __syncthreads();
    for (int i = tid; i < NG * LATD; i += 128) {
        int g = i / LATD, j = i - g * LATD;
        float s = __ldg(b1 + j);
        for (int f = 0; f < LATD + GF; f++) s = fmaf(sp[g][f], __ldg(w1 + f * LATD + j), s);
        sh[g][j] = fmaxf(s, 0.f);
    }
    __syncthreads();
    for (int i = tid; i < NG * LATD; i += 128) {
        int g = i / LATD, j = i - g * LATD;
        float s = __ldg(b2 + j);
        for (int f = 0; f < LATD; f++) s = fmaf(sh[g][f], __ldg(w2 + f * LATD + j), s);
        sh2[g][j] = fmaxf(s, 0.f);
    }
    __syncthreads();
    for (int g = tid; g < NG; g += 128) {
        float s = __ldg(b3);
        for (int f = 0; f < LATD; f++) s = fmaf(sh2[g][f], __ldg(w3 + f), s);
        out[g] = s;
    }
}

extern "C" void kernel_launch(void* const* d_in, const int* in_sizes, int n_in,
                              void* d_out, int out_size) {
    const float* x     = (const float*)d_in[0];
    const void*  ei    = d_in[1];
    const void*  batch = d_in[2];
    const float* u     = (const float*)d_in[3];
    const float* l0w1  = (const float*)d_in[4];
    const float* l0b1  = (const float*)d_in[5];
    const float* l0w2  = (const float*)d_in[6];
    const float* l0b2  = (const float*)d_in[7];
    const float* l0w3  = (const float*)d_in[8];
    const float* l0b3  = (const float*)d_in[9];
    const float* l1w1  = (const float*)d_in[10];
    const float* l1b1  = (const float*)d_in[11];
    const float* l1w2  = (const float*)d_in[12];
    const float* l1b2  = (const float*)d_in[13];
    const float* l1w3  = (const float*)d_in[14];
    const float* l1b3  = (const float*)d_in[15];
    const float* lw1   = (const float*)d_in[16];
    const float* lb1   = (const float*)d_in[17];
    const float* lw2   = (const float*)d_in[18];
    const float* lb2   = (const float*)d_in[19];
    const float* lw3   = (const float*)d_in[20];
    const float* lb3   = (const float*)d_in[21];
    float* out = (float*)d_out;

    const int SMEM_EDGE = (128 + 2 * HID * STR + 6400) * (int)sizeof(float); // 184512 B
    cudaFuncSetAttribute(k_edge, cudaFuncAttributeMaxDynamicSharedMemorySize, SMEM_EDGE);

    float* x1p = nullptr;
    cudaGetSymbolAddress((void**)&x1p, g_x1);

    k_probe<<<1, 1>>>(ei);
    k_convert<<<(NE + 255) / 256, 256>>>(ei, batch);
    k_zero_all<<<512, 256>>>();
    k_counts<<<(NE + 255) / 256, 256>>>();
    k_node_pre<NF><<<(NN * (HID / 4) + 255) / 256, 256>>>(x, l0w1, l0b1);
    k_edge<<<NE / TE, 256, SMEM_EDGE>>>(l0w2, l0b2, l0w3, l0b3);
    k_fin0<<<(NN * LATD + 255) / 256, 256>>>();
    k_zero_acc<<<512, 256>>>();
    k_node_pre<LATD><<<(NN * (HID / 4) + 255) / 256, 256>>>(x1p, l1w1, l1b1);
    k_edge<<<NE / TE, 256, SMEM_EDGE>>>(l1w2, l1b2, l1w3, l1b3);
    k_fin1<<<(NN * LATD + 255) / 256, 256>>>();
    k_head<<<1, 128>>>(u, lw1, lb1, lw2, lb2, lw3, lb3, out);
}

// round 8
// speedup vs baseline: 1.0012x; 1.0012x over previous
#include <cuda_runtime.h>

#define NN   50000
#define NG   32
#define NF   16
#define GF   2
#define HID  300
#define LATD 100
#define NE   800000
#define TE   64
#define STR  66   // smem row stride for transposed tiles (bank-conflict pad, even for LDS.64)

typedef unsigned long long u64;
typedef long long i64;

// -------- scratch (device globals; no allocation allowed) --------
__device__ float g_B[NN * HID];     // per-node  x @ W_bot
__device__ float g_C[NN * HID];     // per-node  x @ (W_top - W_bot) + b1
__device__ float g_acc[NN * LATD];  // scatter accumulator
__device__ float g_x1[NN * LATD];   // node features between layers
__device__ float g_cnt[NN];         // in-degree (float for direct divide)
__device__ float g_pool[NG * LATD]; // graph pooling sums
__device__ float g_gcnt[NG];        // nodes per graph
__device__ int   g_src[NE];         // normalized int32 edge sources
__device__ int   g_dst[NE];         // normalized int32 edge dests
__device__ int   g_batch[NN];       // normalized int32 batch ids
__device__ int   g_is64;            // dtype probe result

// -------- f32x2 helpers (FFMA2: 2x FP32 FMA throughput, PTX-only) --------
__device__ __forceinline__ u64 splat2(float v) {
    u64 r; unsigned iv = __float_as_uint(v);
    asm("mov.b64 %0, {%1, %1};" : "=l"(r) : "r"(iv));
    return r;
}
__device__ __forceinline__ u64 fma2(u64 a, u64 b, u64 c) {
    u64 d;
    asm("fma.rn.f32x2 %0, %1, %2, %3;" : "=l"(d) : "l"(a), "l"(b), "l"(c));
    return d;
}
__device__ __forceinline__ void unpack2(u64 v, float& lo, float& hi) {
    unsigned a, b;
    asm("mov.b64 {%0, %1}, %2;" : "=r"(a), "=r"(b) : "l"(v));
    lo = __uint_as_float(a); hi = __uint_as_float(b);
}

// -------- dtype probe: are index inputs int64 or int32? --------
// If truly int64: every value < 50000 < 2^32. If int32 narrowed: a u64 read
// combines two random indices in [0,50000) -> >= 2^32 w.p. ~1 per element.
__global__ void k_probe(const void* ei) {
    const u64* p = (const u64*)ei;
    int is64 = 1;
    for (int i = 0; i < 16; i++)
        if (p[i] >= (1ull << 32)) is64 = 0;
    g_is64 = is64;
}

// Normalize edge_index + batch into int32 device arrays (handles both dtypes).
__global__ void k_convert(const void* ei, const void* batch) {
    int i = blockIdx.x * blockDim.x + threadIdx.x;
    if (g_is64) {
        const i64* e = (const i64*)ei;
        const i64* b = (const i64*)batch;
        if (i < NE) { g_src[i] = (int)e[i]; g_dst[i] = (int)e[NE + i]; }
        if (i < NN) g_batch[i] = (int)b[i];
    } else {
        const int* e = (const int*)ei;
        const int* b = (const int*)batch;
        if (i < NE) { g_src[i] = e[i]; g_dst[i] = e[NE + i]; }
        if (i < NN) g_batch[i] = b[i];
    }
}

// -------- zero / count kernels --------
__global__ void k_zero_all() {
    int i = blockIdx.x * blockDim.x + threadIdx.x;
    int st = gridDim.x * blockDim.x;
    for (int j = i; j < NN * LATD; j += st) g_acc[j] = 0.f;
    for (int j = i; j < NN; j += st) g_cnt[j] = 0.f;
    for (int j = i; j < NG * LATD; j += st) g_pool[j] = 0.f;
    for (int j = i; j < NG; j += st) g_gcnt[j] = 0.f;
}
__global__ void k_zero_acc() {
    int i = blockIdx.x * blockDim.x + threadIdx.x;
    int st = gridDim.x * blockDim.x;
    for (int j = i; j < NN * LATD; j += st) g_acc[j] = 0.f;
}
__global__ void k_counts() {
    int i = blockIdx.x * blockDim.x + threadIdx.x;
    if (i < NE) atomicAdd(&g_cnt[g_dst[i]], 1.f);
    if (i < NN) atomicAdd(&g_gcnt[g_batch[i]], 1.f);
}

// -------- node precompute: B = x@W_bot, C = x@(W_top - W_bot) + b1 --------
// thread computes 4 consecutive h's (float4 weight loads; 300 = 75*4)
template <int INF>
__global__ void k_node_pre(const float* __restrict__ x,
                           const float* __restrict__ w1,
                           const float* __restrict__ b1) {
    int i = blockIdx.x * blockDim.x + threadIdx.x;
    if (i >= NN * (HID / 4)) return;
    int n = i / (HID / 4);
    int h4 = (i - n * (HID / 4)) * 4;
    const float* xr = x + n * INF;
    float4 a = make_float4(0.f, 0.f, 0.f, 0.f);
    float4 b = make_float4(0.f, 0.f, 0.f, 0.f);
#pragma unroll 8
    for (int f = 0; f < INF; f++) {
        float xv = __ldg(xr + f);
        float4 wt = *(const float4*)(w1 + f * HID + h4);
        float4 wb = *(const float4*)(w1 + (INF + f) * HID + h4);
        a.x = fmaf(xv, wt.x, a.x); a.y = fmaf(xv, wt.y, a.y);
        a.z = fmaf(xv, wt.z, a.z); a.w = fmaf(xv, wt.w, a.w);
        b.x = fmaf(xv, wb.x, b.x); b.y = fmaf(xv, wb.y, b.y);
        b.z = fmaf(xv, wb.z, b.z); b.w = fmaf(xv, wb.w, b.w);
    }
    float4 bb = *(const float4*)(b1 + h4);
    int o = n * HID + h4;
    *(float4*)(g_B + o) = b;
    float4 c = make_float4(a.x - b.x + bb.x, a.y - b.y + bb.y,
                           a.z - b.z + bb.z, a.w - b.w + bb.w);
    *(float4*)(g_C + o) = c;
}

// -------- fused edge MLP: 64 edges/CTA, FFMA2 register-tiled GEMM chain --------
// h1 = relu(C[dst] + B[src])            [64,300]  (smem, transposed)
// h2 = relu(h1 @ w2 + b2)               [64,300]  (smem, transposed)
// m  = h2 @ w3 + b3                     [64,100]  -> atomic scatter to g_acc[dst]
__global__ void __launch_bounds__(256) k_edge(const float* __restrict__ w2,
                                              const float* __restrict__ b2,
                                              const float* __restrict__ w3,
                                              const float* __restrict__ b3) {
    extern __shared__ float smem[];
    int* s_src = (int*)smem;            // 64 ints
    int* s_dst = s_src + TE;            // 64 ints
    float* shA  = smem + 128;           // [300][66] h1^T
    float* shH2 = shA + HID * STR;      // [300][66] h2^T
    float* shB  = shH2 + HID * STR;     // weight staging: 2*10*320 floats (reused 2*10*128)

    const int tid = threadIdx.x;
    const int tx = tid & 31, ty = tid >> 5;
    const int e0 = blockIdx.x * TE;

    if (tid < TE) {
        s_src[tid] = g_src[e0 + tid];
        s_dst[tid] = g_dst[e0 + tid];
    }
    __syncthreads();

    // gather: h1^T[k][r] = relu(C[dst_r][k] + B[src_r][k]), float2 global loads
    for (int idx = tid; idx < TE * (HID / 2); idx += 256) {
        int r = idx / (HID / 2);
        int k2 = (idx - r * (HID / 2)) * 2;
        const float2 cv = *(const float2*)(g_C + s_dst[r] * HID + k2);
        const float2 bv = *(const float2*)(g_B + s_src[r] * HID + k2);
        shA[k2 * STR + r]       = fmaxf(cv.x + bv.x, 0.f);
        shA[(k2 + 1) * STR + r] = fmaxf(cv.y + bv.y, 0.f);
    }
    __syncthreads();

    // ---------------- GEMM1: [64,300] @ w2[300,300] (cols padded to 320) ----------------
    // thread tile: 8 rows (4 f32x2 pairs) x 10 cols (5 col-pairs, stride 64)
    u64 acc[4][5][2];
#pragma unroll
    for (int p = 0; p < 4; p++)
#pragma unroll
        for (int t = 0; t < 5; t++) { acc[p][t][0] = 0ull; acc[p][t][1] = 0ull; }

    float sreg[13];
#pragma unroll
    for (int q = 0; q < 13; q++) {
        int i2 = tid + 256 * q;
        if (i2 < 3200) {
            int kk = i2 / 320, j = i2 - kk * 320;
            sreg[q] = (j < HID) ? __ldg(w2 + kk * HID + j) : 0.f;
        }
    }
#pragma unroll
    for (int q = 0; q < 13; q++) {
        int i2 = tid + 256 * q;
        if (i2 < 3200) shB[i2] = sreg[q];
    }
    __syncthreads();

    int buf = 0;
#pragma unroll 1
    for (int kc = 0; kc < 30; kc++) {
        int k0 = kc * 10;
        if (kc < 29) {
            int kn = k0 + 10;
#pragma unroll
            for (int q = 0; q < 13; q++) {
                int i2 = tid + 256 * q;
                if (i2 < 3200) {
                    int kk = i2 / 320, j = i2 - kk * 320;
                    sreg[q] = (j < HID) ? __ldg(w2 + (kn + kk) * HID + j) : 0.f;
                }
            }
        }
        const float* bBase = shB + buf * 3200;
#pragma unroll
        for (int kk = 0; kk < 10; kk++) {
            const float* aR = shA + (k0 + kk) * STR + ty * 8;
            u64 av[4];
#pragma unroll
            for (int p = 0; p < 4; p++) av[p] = *(const u64*)(aR + 2 * p);
            const float* bR = bBase + kk * 320 + tx * 2;
#pragma unroll
            for (int t = 0; t < 5; t++) {
                float2 bv = *(const float2*)(bR + 64 * t);
                u64 bx = splat2(bv.x), by = splat2(bv.y);
#pragma unroll
                for (int p = 0; p < 4; p++) {
                    acc[p][t][0] = fma2(av[p], bx, acc[p][t][0]);
                    acc[p][t][1] = fma2(av[p], by, acc[p][t][1]);
                }
            }
        }
        if (kc < 29) {
#pragma unroll
            for (int q = 0; q < 13; q++) {
                int i2 = tid + 256 * q;
                if (i2 < 3200) shB[(buf ^ 1) * 3200 + i2] = sreg[q];
            }
        }
        __syncthreads();
        buf ^= 1;
    }

    // epilogue GEMM1: h2^T = relu(acc + b2)
#pragma unroll
    for (int t = 0; t < 5; t++) {
#pragma unroll
        for (int c = 0; c < 2; c++) {
            int j = 64 * t + tx * 2 + c;
            if (j < HID) {
                float bb = __ldg(b2 + j);
#pragma unroll
                for (int p = 0; p < 4; p++) {
                    float lo, hi; unpack2(acc[p][t][c], lo, hi);
                    int r0 = ty * 8 + 2 * p;
                    float2 v;
                    v.x = fmaxf(lo + bb, 0.f);
                    v.y = fmaxf(hi + bb, 0.f);
                    *(float2*)(shH2 + j * STR + r0) = v;
                }
            }
        }
    }

    // prefetch GEMM2 chunk 0 (registers only) while epilogue drains
    float sreg2[5];
#pragma unroll
    for (int q = 0; q < 5; q++) {
        int i2 = tid + 256 * q;
        if (i2 < 1280) {
            int kk = i2 / 128, j = i2 - kk * 128;
            sreg2[q] = (j < LATD) ? __ldg(w3 + kk * LATD + j) : 0.f;
        }
    }
    __syncthreads();   // shH2 writes + shB reads complete
#pragma unroll
    for (int q = 0; q < 5; q++) {
        int i2 = tid + 256 * q;
        if (i2 < 1280) shB[i2] = sreg2[q];
    }
    __syncthreads();

    // ---------------- GEMM2: [64,300] @ w3[300,100] (cols padded to 128) ----------------
    u64 accB[4][2][2];
#pragma unroll
    for (int p = 0; p < 4; p++)
#pragma unroll
        for (int t = 0; t < 2; t++) { accB[p][t][0] = 0ull; accB[p][t][1] = 0ull; }

    buf = 0;
#pragma unroll 1
    for (int kc = 0; kc < 30; kc++) {
        int k0 = kc * 10;
        if (kc < 29) {
            int kn = k0 + 10;
#pragma unroll
            for (int q = 0; q < 5; q++) {
                int i2 = tid + 256 * q;
                if (i2 < 1280) {
                    int kk = i2 / 128, j = i2 - kk * 128;
                    sreg2[q] = (j < LATD) ? __ldg(w3 + (kn + kk) * LATD + j) : 0.f;
                }
            }
        }
        const float* bBase = shB + buf * 1280;
#pragma unroll
        for (int kk = 0; kk < 10; kk++) {
            const float* aR = shH2 + (k0 + kk) * STR + ty * 8;
            u64 av[4];
#pragma unroll
            for (int p = 0; p < 4; p++) av[p] = *(const u64*)(aR + 2 * p);
            const float* bR = bBase + kk * 128 + tx * 2;
#pragma unroll
            for (int t = 0; t < 2; t++) {
                float2 bv = *(const float2*)(bR + 64 * t);
                u64 bx = splat2(bv.x), by = splat2(bv.y);
#pragma unroll
                for (int p = 0; p < 4; p++) {
                    accB[p][t][0] = fma2(av[p], bx, accB[p][t][0]);
                    accB[p][t][1] = fma2(av[p], by, accB[p][t][1]);
                }
            }
        }
        if (kc < 29) {
#pragma unroll
            for (int q = 0; q < 5; q++) {
                int i2 = tid + 256 * q;
                if (i2 < 1280) shB[(buf ^ 1) * 1280 + i2] = sreg2[q];
            }
        }
        __syncthreads();
        buf ^= 1;
    }

    // epilogue GEMM2: m = acc + b3, atomic scatter-sum to g_acc[dst]
#pragma unroll
    for (int t = 0; t < 2; t++) {
#pragma unroll
        for (int c = 0; c < 2; c++) {
            int j = 64 * t + tx * 2 + c;
            if (j < LATD) {
                float b3j = __ldg(b3 + j);
#pragma unroll
                for (int p = 0; p < 4; p++) {
                    float lo, hi; unpack2(accB[p][t][c], lo, hi);
                    int r0 = ty * 8 + 2 * p;
                    atomicAdd(g_acc + s_dst[r0] * LATD + j,     lo + b3j);
                    atomicAdd(g_acc + s_dst[r0 + 1] * LATD + j, hi + b3j);
                }
            }
        }
    }
}

// -------- finalize: scatter-mean + relu --------
__global__ void k_fin0() {
    int i = blockIdx.x * blockDim.x + threadIdx.x;
    if (i >= NN * LATD) return;
    int n = i / LATD;
    float v = g_acc[i] / fmaxf(g_cnt[n], 1.f);
    g_x1[i] = fmaxf(v, 0.f);
}
__global__ void k_fin1() {
    int i = blockIdx.x * blockDim.x + threadIdx.x;
    if (i >= NN * LATD) return;
    int n = i / LATD;
    int j = i - n * LATD;
    float v = fmaxf(g_acc[i] / fmaxf(g_cnt[n], 1.f), 0.f);
    atomicAdd(g_pool + g_batch[n] * LATD + j, v);
}

// -------- head MLP: [32,102] -> 100 -> 100 -> 1 (single CTA) --------
__global__ void k_head(const float* __restrict__ u,
                       const float* __restrict__ w1, const float* __restrict__ b1,
                       const float* __restrict__ w2, const float* __restrict__ b2,
                       const float* __restrict__ w3, const float* __restrict__ b3,
                       float* __restrict__ out) {
    __shared__ float sp[NG][LATD + GF];
    __shared__ float sh[NG][LATD];
    __shared__ float sh2[NG][LATD];
    int tid = threadIdx.x;  // 128
    for (int i = tid; i < NG * LATD; i += 128) {
        int g = i / LATD, j = i - g * LATD;
        sp[g][j] = g_pool[i] / fmaxf(g_gcnt[g], 1.f);
    }
    for (int i = tid; i < NG * GF; i += 128) {
        int g = i / GF;
        sp[g][LATD + (i - g * GF)] = u[i];
    }
    __syncthreads();
    for (int i = tid; i < NG * LATD; i += 128) {
        int g = i / LATD, j = i - g * LATD;
        float s = __ldg(b1 + j);
        for (int f = 0; f < LATD + GF; f++) s = fmaf(sp[g][f], __ldg(w1 + f * LATD + j), s);
        sh[g][j] = fmaxf(s, 0.f);
    }
    __syncthreads();
    for (int i = tid; i < NG * LATD; i += 128) {
        int g = i / LATD, j = i - g * LATD;
        float s = __ldg(b2 + j);
        for (int f = 0; f < LATD; f++) s = fmaf(sh[g][f], __ldg(w2 + f * LATD + j), s);
        sh2[g][j] = fmaxf(s, 0.f);
    }
    __syncthreads();
    for (int g = tid; g < NG; g += 128) {
        float s = __ldg(b3);
        for (int f = 0; f < LATD; f++) s = fmaf(sh2[g][f], __ldg(w3 + f), s);
        out[g] = s;
    }
}

extern "C" void kernel_launch(void* const* d_in, const int* in_sizes, int n_in,
                              void* d_out, int out_size) {
    const float* x     = (const float*)d_in[0];
    const void*  ei    = d_in[1];
    const void*  batch = d_in[2];
    const float* u     = (const float*)d_in[3];
    const float* l0w1  = (const float*)d_in[4];
    const float* l0b1  = (const float*)d_in[5];
    const float* l0w2  = (const float*)d_in[6];
    const float* l0b2  = (const float*)d_in[7];
    const float* l0w3  = (const float*)d_in[8];
    const float* l0b3  = (const float*)d_in[9];
    const float* l1w1  = (const float*)d_in[10];
    const float* l1b1  = (const float*)d_in[11];
    const float* l1w2  = (const float*)d_in[12];
    const float* l1b2  = (const float*)d_in[13];
    const float* l1w3  = (const float*)d_in[14];
    const float* l1b3  = (const float*)d_in[15];
    const float* lw1   = (const float*)d_in[16];
    const float* lb1   = (const float*)d_in[17];
    const float* lw2   = (const float*)d_in[18];
    const float* lb2   = (const float*)d_in[19];
    const float* lw3   = (const float*)d_in[20];
    const float* lb3   = (const float*)d_in[21];
    float* out = (float*)d_out;

    const int SMEM_EDGE = (128 + 2 * HID * STR + 6400) * (int)sizeof(float); // 184512 B
    cudaFuncSetAttribute(k_edge, cudaFuncAttributeMaxDynamicSharedMemorySize, SMEM_EDGE);

    float* x1p = nullptr;
    cudaGetSymbolAddress((void**)&x1p, g_x1);

    k_probe<<<1, 1>>>(ei);
    k_convert<<<(NE + 255) / 256, 256>>>(ei, batch);
    k_zero_all<<<512, 256>>>();
    k_counts<<<(NE + 255) / 256, 256>>>();
    k_node_pre<NF><<<(NN * (HID / 4) + 255) / 256, 256>>>(x, l0w1, l0b1);
    k_edge<<<NE / TE, 256, SMEM_EDGE>>>(l0w2, l0b2, l0w3, l0b3);
    k_fin0<<<(NN * LATD + 255) / 256, 256>>>();
    k_zero_acc<<<512, 256>>>();
    k_node_pre<LATD><<<(NN * (HID / 4) + 255) / 256, 256>>>(x1p, l1w1, l1b1);
    k_edge<<<NE / TE, 256, SMEM_EDGE>>>(l1w2, l1b2, l1w3, l1b3);
    k_fin1<<<(NN * LATD + 255) / 256, 256>>>();
    k_head<<<1, 128>>>(u, lw1, lb1, lw2, lb2, lw3, lb3, out);
}